// round 13
// baseline (speedup 1.0000x reference)
#include <cuda_runtime.h>
#include <cuda_bf16.h>
#include <math.h>

#define MAXN 100352
#define MAXE 1600000
#define SCAN_CHUNK 1024

__device__ int   g_cnt[MAXN];        // static zero-init; re-zeroed by scan each call
__device__ int   g_cursor[MAXN];
__device__ int   g_off[MAXN + 1];
__device__ int   g_bstate[128];      // lookback state: (status<<24)|value; re-zeroed by gemm
__device__ int   g_srcsort[MAXE];
__device__ float g_msgvar[(size_t)MAXN * 128]; // [N][0:64)=msg, [64:128)=var

// ---------------------------------------------------------------------------
// In-block dtype detect: int64 little-endian (values < 2^31) => first 256 odd
// int32 words are all zero. Hot 1KB; every block computes the same answer.
// ---------------------------------------------------------------------------
__device__ __forceinline__ int block_detect_is64(const int* __restrict__ ei32,
                                                 int* s_flag) {
    if (threadIdx.x == 0) *s_flag = 1;
    __syncthreads();
    if (threadIdx.x < 256) {
        if (ei32[2 * threadIdx.x + 1] != 0) *s_flag = 0;   // benign race
    }
    __syncthreads();
    return *s_flag;
}

// ---------------------------------------------------------------------------
// Pass 1: histogram of dst degrees
// ---------------------------------------------------------------------------
__global__ void ra_hist_kernel(const int* __restrict__ ei32, int E, int N) {
    __shared__ int s_flag;
    int is64 = block_detect_is64(ei32, &s_flag);
    int e = blockIdx.x * blockDim.x + threadIdx.x;
    if (e < E) {
        int d = is64 ? ei32[2 * ((size_t)E + e)] : ei32[(size_t)E + e];
        if ((unsigned)d < (unsigned)N) atomicAdd(&g_cnt[d], 1);
    }
}

// ---------------------------------------------------------------------------
// Pass 2: single-pass exclusive scan with decoupled lookback.
// Also re-zeroes g_cnt (replacing the init kernel) and seeds g_cursor.
// status: 0 = invalid, 1 = aggregate ready, 2 = inclusive prefix ready.
// ---------------------------------------------------------------------------
__global__ void __launch_bounds__(256) ra_scan_kernel(int nb, int N) {
    __shared__ int wpre[8];
    __shared__ int s_excl;
    int tid = threadIdx.x;
    int lane = tid & 31, w = tid >> 5;
    int base = blockIdx.x * SCAN_CHUNK + tid * 4;

    int c[4];
    int s = 0;
#pragma unroll
    for (int j = 0; j < 4; ++j) {
        int i = base + j;
        c[j] = (i < N) ? g_cnt[i] : 0;
        if (i < N) g_cnt[i] = 0;            // restore for next call
        s += c[j];
    }
    int incl = s;
#pragma unroll
    for (int o = 1; o < 32; o <<= 1) {
        int u = __shfl_up_sync(0xffffffffu, incl, o);
        if (lane >= o) incl += u;
    }
    if (lane == 31) wpre[w] = incl;
    __syncthreads();

    // block total
    int btot = 0;
#pragma unroll
    for (int i = 0; i < 8; ++i) btot += wpre[i];

    // publish + lookback (thread 0)
    if (tid == 0) {
        if (blockIdx.x == 0) {
            atomicExch(&g_bstate[0], (2 << 24) | btot);
            s_excl = 0;
        } else {
            atomicExch(&g_bstate[blockIdx.x], (1 << 24) | btot);
            int excl = 0;
            int j = blockIdx.x - 1;
            while (true) {
                int st = atomicAdd(&g_bstate[j], 0);
                int tag = st >> 24;
                if (tag == 0) continue;          // spin: predecessor not ready
                excl += st & 0xFFFFFF;
                if (tag == 2) break;             // hit a full prefix
                --j;
            }
            s_excl = excl;
            atomicExch(&g_bstate[blockIdx.x], (2 << 24) | (excl + btot));
        }
    }
    __syncthreads();
    int bbase = s_excl;

    if (blockIdx.x == nb - 1 && tid == 0) g_off[N] = bbase + btot;

    int run = bbase + incl - s;
#pragma unroll
    for (int i = 0; i < 8; ++i) if (i < w) run += wpre[i];
#pragma unroll
    for (int j = 0; j < 4; ++j) {
        int i = base + j;
        if (i < N) { g_off[i] = run; g_cursor[i] = run; }
        run += c[j];
    }
}

// ---------------------------------------------------------------------------
// Pass 3: scatter src into dst-sorted order; cursor pre-seeded with offsets.
// ---------------------------------------------------------------------------
__global__ void ra_scatter_kernel(const int* __restrict__ ei32, int E, int N) {
    __shared__ int s_flag;
    int is64 = block_detect_is64(ei32, &s_flag);
    int e = blockIdx.x * blockDim.x + threadIdx.x;
    if (e < E) {
        int s = is64 ? ei32[2 * (size_t)e] : ei32[e];
        int d = is64 ? ei32[2 * ((size_t)E + e)] : ei32[(size_t)E + e];
        if ((unsigned)d < (unsigned)N && (unsigned)s < (unsigned)N) {
            int p = atomicAdd(&g_cursor[d], 1);
            g_srcsort[p] = s;
        }
    }
}

// ---------------------------------------------------------------------------
// Pass 4: one warp per dst node. Half-warp h owns edges b+2t+h; lane owns
// 4 dims (float4). Software-pipelined; direct exp (shift-invariant softmax).
// (R10 body, best measured.)
// ---------------------------------------------------------------------------
__global__ void __launch_bounds__(256)
ra_agg_kernel(const float* __restrict__ x, int N) {
    int gtid = blockIdx.x * blockDim.x + threadIdx.x;
    int n = gtid >> 5;
    if (n >= N) return;
    int lane = threadIdx.x & 31;
    int half = lane >> 4;
    int hl   = lane & 15;

    int b = g_off[n];
    int e = g_off[n + 1];
    int cnt = e - b;

    float* row = g_msgvar + (size_t)n * 128;
    if (cnt == 0) {
        if (half == 0) {
            *reinterpret_cast<float4*>(row + 4 * hl)      = make_float4(0.f, 0.f, 0.f, 0.f);
            *reinterpret_cast<float4*>(row + 64 + 4 * hl) = make_float4(0.f, 0.f, 0.f, 0.f);
        }
        return;
    }

    float4 xd = *reinterpret_cast<const float4*>(x + (size_t)n * 64 + 4 * hl);

    int niter = (cnt + 1) >> 1;

    float denom = 0.f;
    float4 mg = make_float4(0.f, 0.f, 0.f, 0.f);
    float4 s  = make_float4(0.f, 0.f, 0.f, 0.f);
    float4 q  = make_float4(0.f, 0.f, 0.f, 0.f);

    int  i_cur = b + half;
    bool v_cur = (i_cur < e);
    int  sidx  = g_srcsort[v_cur ? i_cur : b];
    float4 xs  = *reinterpret_cast<const float4*>(x + (size_t)sidx * 64 + 4 * hl);

    for (int t = 0; t < niter; ++t) {
        int  i_nxt = b + 2 * (t + 1) + half;
        bool v_nxt = (t + 1 < niter) && (i_nxt < e);
        int  snxt  = g_srcsort[v_nxt ? i_nxt : b];
        float4 xn  = *reinterpret_cast<const float4*>(x + (size_t)snxt * 64 + 4 * hl);

        float p = fmaf(xs.x, xd.x, fmaf(xs.y, xd.y, fmaf(xs.z, xd.z, xs.w * xd.w)));
        p += __shfl_xor_sync(0xffffffffu, p, 8);
        p += __shfl_xor_sync(0xffffffffu, p, 4);
        p += __shfl_xor_sync(0xffffffffu, p, 2);
        p += __shfl_xor_sync(0xffffffffu, p, 1);

        float w = v_cur ? __expf(p * 0.125f) : 0.f;
        denom += w;
        mg.x = fmaf(w, xs.x, mg.x);
        mg.y = fmaf(w, xs.y, mg.y);
        mg.z = fmaf(w, xs.z, mg.z);
        mg.w = fmaf(w, xs.w, mg.w);
        if (v_cur) {
            s.x += xs.x; s.y += xs.y; s.z += xs.z; s.w += xs.w;
            q.x = fmaf(xs.x, xs.x, q.x);
            q.y = fmaf(xs.y, xs.y, q.y);
            q.z = fmaf(xs.z, xs.z, q.z);
            q.w = fmaf(xs.w, xs.w, q.w);
        }
        xs = xn;
        v_cur = v_nxt;
    }

    denom += __shfl_xor_sync(0xffffffffu, denom, 16);
    mg.x += __shfl_xor_sync(0xffffffffu, mg.x, 16);
    mg.y += __shfl_xor_sync(0xffffffffu, mg.y, 16);
    mg.z += __shfl_xor_sync(0xffffffffu, mg.z, 16);
    mg.w += __shfl_xor_sync(0xffffffffu, mg.w, 16);
    s.x  += __shfl_xor_sync(0xffffffffu, s.x, 16);
    s.y  += __shfl_xor_sync(0xffffffffu, s.y, 16);
    s.z  += __shfl_xor_sync(0xffffffffu, s.z, 16);
    s.w  += __shfl_xor_sync(0xffffffffu, s.w, 16);
    q.x  += __shfl_xor_sync(0xffffffffu, q.x, 16);
    q.y  += __shfl_xor_sync(0xffffffffu, q.y, 16);
    q.z  += __shfl_xor_sync(0xffffffffu, q.z, 16);
    q.w  += __shfl_xor_sync(0xffffffffu, q.w, 16);

    if (half == 0) {
        float invD = 1.0f / denom;
        float invc = 1.0f / (float)cnt;
        float4 mean = make_float4(s.x * invc, s.y * invc, s.z * invc, s.w * invc);
        float4 var;
        var.x = fmaxf(fmaf(-mean.x, mean.x, q.x * invc), 0.f);
        var.y = fmaxf(fmaf(-mean.y, mean.y, q.y * invc), 0.f);
        var.z = fmaxf(fmaf(-mean.z, mean.z, q.z * invc), 0.f);
        var.w = fmaxf(fmaf(-mean.w, mean.w, q.w * invc), 0.f);

        *reinterpret_cast<float4*>(row + 4 * hl) =
            make_float4(mg.x * invD, mg.y * invD, mg.z * invD, mg.w * invD);
        *reinterpret_cast<float4*>(row + 64 + 4 * hl) = var;
    }
}

// ---------------------------------------------------------------------------
// Pass 5: fused GEMM  out = x@Ws^T + msg@Wn^T + var@Wv^T + (bs+bn+bv)
// Block 0 also re-zeroes g_bstate for the next call (stream-ordered).
// ---------------------------------------------------------------------------
#define PACK2(d, a)        asm("mov.b64 %0, {%1, %1};" : "=l"(d) : "f"(a))
#define UNPACK2(lo, hi, v) asm("mov.b64 {%0, %1}, %2;" : "=f"(lo), "=f"(hi) : "l"(v))
#define FMA2(acc, a, b)    asm("fma.rn.f32x2 %0, %1, %2, %0;" : "+l"(acc) : "l"(a), "l"(b))

__global__ void __launch_bounds__(256)
ra_gemm_kernel(const float* __restrict__ x,
               const float* __restrict__ Ws, const float* __restrict__ bs,
               const float* __restrict__ Wn, const float* __restrict__ bn,
               const float* __restrict__ Wv, const float* __restrict__ bv,
               float* __restrict__ out, int N) {
    __shared__ __align__(16) float Ash[128 * 64];
    __shared__ __align__(16) float Bsh[64 * 64];

    int tid = threadIdx.x;
    int tx = tid & 7;
    int ty = tid >> 3;
    int n0 = blockIdx.x * 128;

    if (blockIdx.x == 0 && tid < 128) g_bstate[tid] = 0;   // reset lookback state

    unsigned long long acc[4][4];
#pragma unroll
    for (int r = 0; r < 4; ++r)
#pragma unroll
        for (int p = 0; p < 4; ++p) acc[r][p] = 0ull;

    for (int kc = 0; kc < 3; ++kc) {
        {
            const float* ap; int pitch, cb;
            if (kc == 0) { ap = x;        pitch = 64;  cb = 0; }
            else         { ap = g_msgvar; pitch = 128; cb = (kc - 1) * 64; }
            for (int i = tid; i < 128 * 64; i += 256) {
                int node = i >> 6, k = i & 63;
                int nn = n0 + node;
                Ash[i] = (nn < N) ? ap[(size_t)nn * pitch + cb + k] : 0.0f;
            }
        }
        {
            const float* wp = (kc == 0) ? Ws : ((kc == 1) ? Wn : Wv);
            for (int i = tid; i < 64 * 64; i += 256) {
                int ii = i >> 6;
                int kk = i & 63;
                int c4 = (ii >> 2) ^ (kk & 15);
                Bsh[kk * 64 + (c4 << 2) + (ii & 3)] = wp[i];
            }
        }
        __syncthreads();

        const float* arow = &Ash[(ty * 4) * 64];
        for (int k0 = 0; k0 < 64; k0 += 16) {
#pragma unroll
            for (int u = 0; u < 16; ++u) {
                int k = k0 + u;
                float a0 = arow[0 * 64 + k];
                float a1 = arow[1 * 64 + k];
                float a2 = arow[2 * 64 + k];
                float a3 = arow[3 * 64 + k];
                unsigned long long A0, A1, A2, A3;
                PACK2(A0, a0); PACK2(A1, a1); PACK2(A2, a2); PACK2(A3, a3);

                int sw0 = (((tx * 2)     ^ u) << 2);
                int sw1 = (((tx * 2 + 1) ^ u) << 2);
                ulonglong2 B0 = *reinterpret_cast<const ulonglong2*>(&Bsh[k * 64 + sw0]);
                ulonglong2 B1 = *reinterpret_cast<const ulonglong2*>(&Bsh[k * 64 + sw1]);

                FMA2(acc[0][0], A0, B0.x); FMA2(acc[0][1], A0, B0.y);
                FMA2(acc[0][2], A0, B1.x); FMA2(acc[0][3], A0, B1.y);
                FMA2(acc[1][0], A1, B0.x); FMA2(acc[1][1], A1, B0.y);
                FMA2(acc[1][2], A1, B1.x); FMA2(acc[1][3], A1, B1.y);
                FMA2(acc[2][0], A2, B0.x); FMA2(acc[2][1], A2, B0.y);
                FMA2(acc[2][2], A2, B1.x); FMA2(acc[2][3], A2, B1.y);
                FMA2(acc[3][0], A3, B0.x); FMA2(acc[3][1], A3, B0.y);
                FMA2(acc[3][2], A3, B1.x); FMA2(acc[3][3], A3, B1.y);
            }
        }
        __syncthreads();
    }

    float bsum[8];
#pragma unroll
    for (int p = 0; p < 8; ++p) {
        int d = tx * 8 + p;
        bsum[p] = bs[d] + bn[d] + bv[d];
    }
#pragma unroll
    for (int r = 0; r < 4; ++r) {
        int n = n0 + ty * 4 + r;
        if (n < N) {
            float o[8];
#pragma unroll
            for (int p = 0; p < 4; ++p) {
                float lo, hi;
                UNPACK2(lo, hi, acc[r][p]);
                o[2 * p]     = lo + bsum[2 * p];
                o[2 * p + 1] = hi + bsum[2 * p + 1];
            }
            float4* dst = reinterpret_cast<float4*>(out + (size_t)n * 64 + tx * 8);
            dst[0] = make_float4(o[0], o[1], o[2], o[3]);
            dst[1] = make_float4(o[4], o[5], o[6], o[7]);
        }
    }
}

// ---------------------------------------------------------------------------
extern "C" void kernel_launch(void* const* d_in, const int* in_sizes, int n_in,
                              void* d_out, int out_size) {
    const float* x  = (const float*)d_in[0];
    const int*   ei = (const int*)d_in[1];
    const float* Ws = (const float*)d_in[2];
    const float* bs = (const float*)d_in[3];
    const float* Wn = (const float*)d_in[4];
    const float* bn = (const float*)d_in[5];
    const float* Wv = (const float*)d_in[6];
    const float* bv = (const float*)d_in[7];
    float* out = (float*)d_out;

    int N = in_sizes[0] / 64;
    int E = in_sizes[1] / 2;
    int nb = (N + SCAN_CHUNK - 1) / SCAN_CHUNK;

    ra_hist_kernel<<<(E + 255) / 256, 256>>>(ei, E, N);
    ra_scan_kernel<<<nb, 256>>>(nb, N);
    ra_scatter_kernel<<<(E + 255) / 256, 256>>>(ei, E, N);
    ra_agg_kernel<<<(N * 32 + 255) / 256, 256>>>(x, N);
    ra_gemm_kernel<<<(N + 127) / 128, 256>>>(x, Ws, bs, Wn, bn, Wv, bv, out, N);
}

// round 14
// speedup vs baseline: 1.0367x; 1.0367x over previous
#include <cuda_runtime.h>
#include <cuda_bf16.h>
#include <math.h>

#define MAXN 100352
#define MAXE 1600000
#define SCAN_CHUNK 1024

__device__ int   g_is64;
__device__ int   g_cnt[MAXN];
__device__ int   g_cursor[MAXN];
__device__ int   g_off[MAXN + 1];
__device__ int   g_bsum[128];
__device__ int   g_srcsort[MAXE];
__device__ float g_msgvar[(size_t)MAXN * 128]; // [N][0:64)=msg, [64:128)=var

// ---------------------------------------------------------------------------
// Pass 0: zero counters; block 0 also detects edge_index dtype
// (int64 little-endian with values < 2^31 => odd int32 words all zero).
// ---------------------------------------------------------------------------
__global__ void ra_init_kernel(const int* __restrict__ ei32, int N) {
    int i = blockIdx.x * blockDim.x + threadIdx.x;
    if (i < N) g_cnt[i] = 0;
    if (blockIdx.x == 0) {
        __shared__ int nz;
        if (threadIdx.x == 0) nz = 0;
        __syncthreads();
        int v = ei32[2 * threadIdx.x + 1];
        if (v != 0) nz = 1;                  // benign race
        __syncthreads();
        if (threadIdx.x == 0) g_is64 = nz ? 0 : 1;
    }
}

__device__ __forceinline__ int load_src(const int* ei32, int E, int e) {
    return g_is64 ? ei32[2 * e] : ei32[e];
}
__device__ __forceinline__ int load_dst(const int* ei32, int E, int e) {
    return g_is64 ? ei32[2 * (E + e)] : ei32[E + e];
}

// ---------------------------------------------------------------------------
__global__ void ra_hist_kernel(const int* __restrict__ ei32, int E, int N) {
    int e = blockIdx.x * blockDim.x + threadIdx.x;
    if (e < E) {
        int d = load_dst(ei32, E, e);
        if ((unsigned)d < (unsigned)N) atomicAdd(&g_cnt[d], 1);
    }
}

// ---------------------------------------------------------------------------
__global__ void __launch_bounds__(256) ra_scan1_kernel(int N) {
    __shared__ int wsum[8];
    int base = blockIdx.x * SCAN_CHUNK + threadIdx.x * 4;
    int s = 0;
#pragma unroll
    for (int j = 0; j < 4; ++j) {
        int i = base + j;
        if (i < N) s += g_cnt[i];
    }
#pragma unroll
    for (int o = 16; o > 0; o >>= 1) s += __shfl_xor_sync(0xffffffffu, s, o);
    if ((threadIdx.x & 31) == 0) wsum[threadIdx.x >> 5] = s;
    __syncthreads();
    if (threadIdx.x == 0) {
        int t = 0;
#pragma unroll
        for (int w = 0; w < 8; ++w) t += wsum[w];
        g_bsum[blockIdx.x] = t;
    }
}

__global__ void __launch_bounds__(256) ra_scan3_kernel(int nb, int N) {
    __shared__ int sb[128];
    __shared__ int wtot[4];
    __shared__ int wpre[8];
    int tid = threadIdx.x;
    int lane = tid & 31, w = tid >> 5;

    {
        int v = (tid < nb) ? g_bsum[tid] : 0;
        int incl = v;
#pragma unroll
        for (int o = 1; o < 32; o <<= 1) {
            int u = __shfl_up_sync(0xffffffffu, incl, o);
            if (lane >= o) incl += u;
        }
        if (lane == 31 && w < 4) wtot[w] = incl;
        __syncthreads();
        if (tid < 128) {
            int wbase = 0;
#pragma unroll
            for (int i = 0; i < 4; ++i) if (i < w) wbase += wtot[i];
            sb[tid] = wbase + incl - v;
        }
        __syncthreads();
        if (blockIdx.x == 0 && tid == 0) g_off[N] = sb[nb - 1] + g_bsum[nb - 1];
    }

    int bbase = sb[blockIdx.x];
    int base = blockIdx.x * SCAN_CHUNK + tid * 4;
    int c[4];
    int s = 0;
#pragma unroll
    for (int j = 0; j < 4; ++j) {
        int i = base + j;
        c[j] = (i < N) ? g_cnt[i] : 0;
        s += c[j];
    }
    int incl = s;
#pragma unroll
    for (int o = 1; o < 32; o <<= 1) {
        int u = __shfl_up_sync(0xffffffffu, incl, o);
        if (lane >= o) incl += u;
    }
    if (lane == 31) wpre[w] = incl;
    __syncthreads();
    int run = bbase + incl - s;
#pragma unroll
    for (int i = 0; i < 8; ++i) if (i < w) run += wpre[i];
#pragma unroll
    for (int j = 0; j < 4; ++j) {
        int i = base + j;
        if (i < N) { g_off[i] = run; g_cursor[i] = run; }
        run += c[j];
    }
}

// ---------------------------------------------------------------------------
__global__ void ra_scatter_kernel(const int* __restrict__ ei32, int E, int N) {
    int e = blockIdx.x * blockDim.x + threadIdx.x;
    if (e < E) {
        int s = load_src(ei32, E, e);
        int d = load_dst(ei32, E, e);
        if ((unsigned)d < (unsigned)N && (unsigned)s < (unsigned)N) {
            int p = atomicAdd(&g_cursor[d], 1);
            g_srcsort[p] = s;
        }
    }
}

// ---------------------------------------------------------------------------
// Packed f32x2 helpers (operate directly on the 64-bit register pairs that
// LDG.128 already produces — no packing cost).
// ---------------------------------------------------------------------------
#define MUL2D(d, a, b)    asm("mul.rn.f32x2 %0, %1, %2;" : "=l"(d) : "l"(a), "l"(b))
#define FMA2A(acc, a, b)  asm("fma.rn.f32x2 %0, %1, %2, %0;" : "+l"(acc) : "l"(a), "l"(b))
#define ADD2A(acc, a)     asm("add.rn.f32x2 %0, %1, %0;" : "+l"(acc) : "l"(a))
#define PACKDUP(d, a)     asm("mov.b64 %0, {%1, %1};" : "=l"(d) : "f"(a))
#define PACK2(d, a)       PACKDUP(d, a)
#define UNPK(lo, hi, v)   asm("mov.b64 {%0, %1}, %2;" : "=f"(lo), "=f"(hi) : "l"(v))
#define UNPACK2(lo, hi, v) UNPK(lo, hi, v)
#define FMA2(acc, a, b)   FMA2A(acc, a, b)

// ---------------------------------------------------------------------------
// Pass 4: one warp per dst node. Half-warp h owns edges b+2t+h; lane owns
// 4 dims (one LDG.128 = two f32x2 register pairs). Main loop has NO validity
// logic (full pairs only; prefetch clamped to e-1); odd tail handled once.
// Direct exp (shift-invariant softmax, logits ~N(0,1)).
// ---------------------------------------------------------------------------
__global__ void __launch_bounds__(256)
ra_agg_kernel(const float* __restrict__ x, int N) {
    int gtid = blockIdx.x * blockDim.x + threadIdx.x;
    int n = gtid >> 5;
    if (n >= N) return;
    int lane = threadIdx.x & 31;
    int half = lane >> 4;
    int hl   = lane & 15;

    int b = g_off[n];
    int e = g_off[n + 1];
    int cnt = e - b;

    float* row = g_msgvar + (size_t)n * 128;
    if (cnt == 0) {
        if (half == 0) {
            *reinterpret_cast<float4*>(row + 4 * hl)      = make_float4(0.f, 0.f, 0.f, 0.f);
            *reinterpret_cast<float4*>(row + 64 + 4 * hl) = make_float4(0.f, 0.f, 0.f, 0.f);
        }
        return;
    }

    ulonglong2 xdv = *reinterpret_cast<const ulonglong2*>(x + (size_t)n * 64 + 4 * hl);

    unsigned long long mg0 = 0, mg1 = 0, s0 = 0, s1 = 0, q0 = 0, q1 = 0;
    float denom = 0.f;

    int full = cnt >> 1;
    ulonglong2 xsv;
    if (full > 0) {
        int sidx = g_srcsort[b + half];
        xsv = *reinterpret_cast<const ulonglong2*>(x + (size_t)sidx * 64 + 4 * hl);
        for (int t = 0; t < full; ++t) {
            int i_nxt = min(b + 2 * (t + 1) + half, e - 1);
            int snxt = g_srcsort[i_nxt];
            ulonglong2 xnv = *reinterpret_cast<const ulonglong2*>(x + (size_t)snxt * 64 + 4 * hl);

            unsigned long long tdp;
            MUL2D(tdp, xsv.x, xdv.x);
            FMA2A(tdp, xsv.y, xdv.y);
            float plo, phi; UNPK(plo, phi, tdp);
            float p = plo + phi;
            p += __shfl_xor_sync(0xffffffffu, p, 8);
            p += __shfl_xor_sync(0xffffffffu, p, 4);
            p += __shfl_xor_sync(0xffffffffu, p, 2);
            p += __shfl_xor_sync(0xffffffffu, p, 1);

            float w = __expf(p * 0.125f);
            denom += w;
            unsigned long long w2; PACKDUP(w2, w);
            FMA2A(mg0, w2, xsv.x); FMA2A(mg1, w2, xsv.y);
            ADD2A(s0, xsv.x);      ADD2A(s1, xsv.y);
            FMA2A(q0, xsv.x, xsv.x); FMA2A(q1, xsv.y, xsv.y);

            xsv = xnv;
        }
    } else {
        int sidx = g_srcsort[e - 1];
        xsv = *reinterpret_cast<const ulonglong2*>(x + (size_t)sidx * 64 + 4 * hl);
    }

    if (cnt & 1) {
        // xsv holds x[srcsort[e-1]] in BOTH halves (loop prefetch clamps to e-1)
        unsigned long long tdp;
        MUL2D(tdp, xsv.x, xdv.x);
        FMA2A(tdp, xsv.y, xdv.y);
        float plo, phi; UNPK(plo, phi, tdp);
        float p = plo + phi;
        p += __shfl_xor_sync(0xffffffffu, p, 8);
        p += __shfl_xor_sync(0xffffffffu, p, 4);
        p += __shfl_xor_sync(0xffffffffu, p, 2);
        p += __shfl_xor_sync(0xffffffffu, p, 1);
        float w = __expf(p * 0.125f);
        if (half == 0) {
            denom += w;
            unsigned long long w2; PACKDUP(w2, w);
            FMA2A(mg0, w2, xsv.x); FMA2A(mg1, w2, xsv.y);
            ADD2A(s0, xsv.x);      ADD2A(s1, xsv.y);
            FMA2A(q0, xsv.x, xsv.x); FMA2A(q1, xsv.y, xsv.y);
        }
    }

    float mgf[4], sf[4], qf[4];
    UNPK(mgf[0], mgf[1], mg0); UNPK(mgf[2], mgf[3], mg1);
    UNPK(sf[0],  sf[1],  s0);  UNPK(sf[2],  sf[3],  s1);
    UNPK(qf[0],  qf[1],  q0);  UNPK(qf[2],  qf[3],  q1);

    denom += __shfl_xor_sync(0xffffffffu, denom, 16);
#pragma unroll
    for (int j = 0; j < 4; ++j) {
        mgf[j] += __shfl_xor_sync(0xffffffffu, mgf[j], 16);
        sf[j]  += __shfl_xor_sync(0xffffffffu, sf[j], 16);
        qf[j]  += __shfl_xor_sync(0xffffffffu, qf[j], 16);
    }

    if (half == 0) {
        float invD = 1.0f / denom;
        float invc = 1.0f / (float)cnt;
        float4 var;
        float m0 = sf[0] * invc, m1 = sf[1] * invc, m2 = sf[2] * invc, m3 = sf[3] * invc;
        var.x = fmaxf(fmaf(-m0, m0, qf[0] * invc), 0.f);
        var.y = fmaxf(fmaf(-m1, m1, qf[1] * invc), 0.f);
        var.z = fmaxf(fmaf(-m2, m2, qf[2] * invc), 0.f);
        var.w = fmaxf(fmaf(-m3, m3, qf[3] * invc), 0.f);

        *reinterpret_cast<float4*>(row + 4 * hl) =
            make_float4(mgf[0] * invD, mgf[1] * invD, mgf[2] * invD, mgf[3] * invD);
        *reinterpret_cast<float4*>(row + 64 + 4 * hl) = var;
    }
}

// ---------------------------------------------------------------------------
// Pass 5: fused GEMM  out = x@Ws^T + msg@Wn^T + var@Wv^T + (bs+bn+bv)
// (R10 configuration: pitch-64 A tile, f32x2 packed FMA.)
// ---------------------------------------------------------------------------
__global__ void __launch_bounds__(256)
ra_gemm_kernel(const float* __restrict__ x,
               const float* __restrict__ Ws, const float* __restrict__ bs,
               const float* __restrict__ Wn, const float* __restrict__ bn,
               const float* __restrict__ Wv, const float* __restrict__ bv,
               float* __restrict__ out, int N) {
    __shared__ __align__(16) float Ash[128 * 64];
    __shared__ __align__(16) float Bsh[64 * 64];

    int tid = threadIdx.x;
    int tx = tid & 7;
    int ty = tid >> 3;
    int n0 = blockIdx.x * 128;

    unsigned long long acc[4][4];
#pragma unroll
    for (int r = 0; r < 4; ++r)
#pragma unroll
        for (int p = 0; p < 4; ++p) acc[r][p] = 0ull;

    for (int kc = 0; kc < 3; ++kc) {
        {
            const float* ap; int pitch, cb;
            if (kc == 0) { ap = x;        pitch = 64;  cb = 0; }
            else         { ap = g_msgvar; pitch = 128; cb = (kc - 1) * 64; }
            for (int i = tid; i < 128 * 64; i += 256) {
                int node = i >> 6, k = i & 63;
                int nn = n0 + node;
                Ash[i] = (nn < N) ? ap[(size_t)nn * pitch + cb + k] : 0.0f;
            }
        }
        {
            const float* wp = (kc == 0) ? Ws : ((kc == 1) ? Wn : Wv);
            for (int i = tid; i < 64 * 64; i += 256) {
                int ii = i >> 6;
                int kk = i & 63;
                int c4 = (ii >> 2) ^ (kk & 15);
                Bsh[kk * 64 + (c4 << 2) + (ii & 3)] = wp[i];
            }
        }
        __syncthreads();

        const float* arow = &Ash[(ty * 4) * 64];
        for (int k0 = 0; k0 < 64; k0 += 16) {
#pragma unroll
            for (int u = 0; u < 16; ++u) {
                int k = k0 + u;
                float a0 = arow[0 * 64 + k];
                float a1 = arow[1 * 64 + k];
                float a2 = arow[2 * 64 + k];
                float a3 = arow[3 * 64 + k];
                unsigned long long A0, A1, A2, A3;
                PACK2(A0, a0); PACK2(A1, a1); PACK2(A2, a2); PACK2(A3, a3);

                int sw0 = (((tx * 2)     ^ u) << 2);
                int sw1 = (((tx * 2 + 1) ^ u) << 2);
                ulonglong2 B0 = *reinterpret_cast<const ulonglong2*>(&Bsh[k * 64 + sw0]);
                ulonglong2 B1 = *reinterpret_cast<const ulonglong2*>(&Bsh[k * 64 + sw1]);

                FMA2(acc[0][0], A0, B0.x); FMA2(acc[0][1], A0, B0.y);
                FMA2(acc[0][2], A0, B1.x); FMA2(acc[0][3], A0, B1.y);
                FMA2(acc[1][0], A1, B0.x); FMA2(acc[1][1], A1, B0.y);
                FMA2(acc[1][2], A1, B1.x); FMA2(acc[1][3], A1, B1.y);
                FMA2(acc[2][0], A2, B0.x); FMA2(acc[2][1], A2, B0.y);
                FMA2(acc[2][2], A2, B1.x); FMA2(acc[2][3], A2, B1.y);
                FMA2(acc[3][0], A3, B0.x); FMA2(acc[3][1], A3, B0.y);
                FMA2(acc[3][2], A3, B1.x); FMA2(acc[3][3], A3, B1.y);
            }
        }
        __syncthreads();
    }

    float bsum[8];
#pragma unroll
    for (int p = 0; p < 8; ++p) {
        int d = tx * 8 + p;
        bsum[p] = bs[d] + bn[d] + bv[d];
    }
#pragma unroll
    for (int r = 0; r < 4; ++r) {
        int n = n0 + ty * 4 + r;
        if (n < N) {
            float o[8];
#pragma unroll
            for (int p = 0; p < 4; ++p) {
                float lo, hi;
                UNPACK2(lo, hi, acc[r][p]);
                o[2 * p]     = lo + bsum[2 * p];
                o[2 * p + 1] = hi + bsum[2 * p + 1];
            }
            float4* dst = reinterpret_cast<float4*>(out + (size_t)n * 64 + tx * 8);
            dst[0] = make_float4(o[0], o[1], o[2], o[3]);
            dst[1] = make_float4(o[4], o[5], o[6], o[7]);
        }
    }
}

// ---------------------------------------------------------------------------
extern "C" void kernel_launch(void* const* d_in, const int* in_sizes, int n_in,
                              void* d_out, int out_size) {
    const float* x  = (const float*)d_in[0];
    const int*   ei = (const int*)d_in[1];
    const float* Ws = (const float*)d_in[2];
    const float* bs = (const float*)d_in[3];
    const float* Wn = (const float*)d_in[4];
    const float* bn = (const float*)d_in[5];
    const float* Wv = (const float*)d_in[6];
    const float* bv = (const float*)d_in[7];
    float* out = (float*)d_out;

    int N = in_sizes[0] / 64;
    int E = in_sizes[1] / 2;
    int nb = (N + SCAN_CHUNK - 1) / SCAN_CHUNK;

    ra_init_kernel<<<(N + 255) / 256, 256>>>(ei, N);
    ra_hist_kernel<<<(E + 255) / 256, 256>>>(ei, E, N);
    ra_scan1_kernel<<<nb, 256>>>(N);
    ra_scan3_kernel<<<nb, 256>>>(nb, N);
    ra_scatter_kernel<<<(E + 255) / 256, 256>>>(ei, E, N);
    ra_agg_kernel<<<(N * 32 + 255) / 256, 256>>>(x, N);
    ra_gemm_kernel<<<(N + 127) / 128, 256>>>(x, Ws, bs, Wn, bn, Wv, bv, out, N);
}